// round 2
// baseline (speedup 1.0000x reference)
#include <cuda_runtime.h>
#include <cuda_bf16.h>
#include <cstdint>

// Problem constants
#define E_ 64
#define A_ 8
#define L_ 2048
#define D_ 128
#define H_ 8
#define DK_ 16
#define EA_ (E_*A_)

// ---------------------------------------------------------------------------
// Device scratch (static allocation only — no cudaMalloc allowed)
// ---------------------------------------------------------------------------
__device__ float g_wkc[129 * 128];                 // Wk_proj @ Wk  -> [d'][h*16+k]
__device__ float g_wvc[129 * 128];                 // Wv_proj @ Wv  -> [d'][h*16+k]
__device__ float g_svec[EA_ * H_ * 128];           // per (e,a,h): score weight vector
__device__ float g_sbias[EA_ * H_];                // per (e,a,h): agent-id score bias

// ---------------------------------------------------------------------------
// P1: combined projection matrices  Wk_comb = Wk_proj @ Wk, same for V.
// grid = 258 blocks (129 d' rows x {K,V}), 128 threads (one output col each)
// ---------------------------------------------------------------------------
__global__ void precompute_comb(const float* __restrict__ Wk_proj,
                                const float* __restrict__ Wk,
                                const float* __restrict__ Wv_proj,
                                const float* __restrict__ Wv)
{
    int b = blockIdx.x;
    int kind = (b >= 129);
    int dp = b - kind * 129;
    const float* proj = kind ? Wv_proj : Wk_proj;   // [129,128] row-major
    const float* wh   = kind ? Wv      : Wk;        // [8,128,16]
    int j = threadIdx.x;          // j = h*16+k
    int h = j >> 4, k = j & 15;
    float acc = 0.f;
    #pragma unroll 8
    for (int m = 0; m < 128; ++m)
        acc += proj[dp * 128 + m] * wh[h * 2048 + m * 16 + k];
    (kind ? g_wvc : g_wkc)[dp * 128 + j] = acc;
}

// ---------------------------------------------------------------------------
// P2: per (e,a) query chain:  q -> qh -> s_vec (with 1/sqrt(DK) folded in)
// grid = 512 blocks, 128 threads
// ---------------------------------------------------------------------------
__global__ void precompute_svec(const float* __restrict__ gc,
                                const float* __restrict__ dep,
                                const float* __restrict__ tbd,
                                const float* __restrict__ load,
                                const float* __restrict__ Wq_proj,  // [386,128]
                                const float* __restrict__ Wq)       // [8,128,16]
{
    int ea = blockIdx.x;
    int e = ea >> 3, a = ea & 7;
    int tid = threadIdx.x;
    __shared__ float qs[128];
    __shared__ float qhs[128];

    // q[d] = q_in @ Wq_proj
    {
        int d = tid;
        float acc = load[e * A_ + a] * Wq_proj[384 * 128 + d]
                  + (float)a          * Wq_proj[385 * 128 + d];
        for (int j = 0; j < 128; ++j) {
            acc += gc [e * 128 + j] * Wq_proj[(      j) * 128 + d];
            acc += dep[e * 128 + j] * Wq_proj[(128 + j) * 128 + d];
            acc += tbd[e * 128 + j] * Wq_proj[(256 + j) * 128 + d];
        }
        qs[d] = acc;
    }
    __syncthreads();
    // qh[h,k]
    {
        int h = tid >> 4, k = tid & 15;
        float acc = 0.f;
        #pragma unroll 8
        for (int d = 0; d < 128; ++d)
            acc += qs[d] * Wq[h * 2048 + d * 16 + k];
        qhs[tid] = acc;
    }
    __syncthreads();
    // s_vec[h,d'] = 0.25 * sum_k Wk_comb[d'][h*16+k] * qh[h,k]
    for (int dp = tid; dp < 129; dp += 128) {
        for (int h = 0; h < H_; ++h) {
            float s = 0.f;
            #pragma unroll
            for (int k = 0; k < 16; ++k)
                s += qhs[h * 16 + k] * g_wkc[dp * 128 + h * 16 + k];
            s *= 0.25f;
            if (dp < 128) g_svec[(ea * H_ + h) * 128 + dp] = s;
            else          g_sbias[ea * H_ + h] = s * (float)a;
        }
    }
}

// ---------------------------------------------------------------------------
// cp.async helpers
// ---------------------------------------------------------------------------
__device__ __forceinline__ void cp_async16(void* dst, const void* src, int nb) {
    unsigned s = (unsigned)__cvta_generic_to_shared(dst);
    asm volatile("cp.async.cg.shared.global [%0], [%1], 16, %2;\n"
                 :: "r"(s), "l"(src), "r"(nb) : "memory");
}
__device__ __forceinline__ void cp_commit() {
    asm volatile("cp.async.commit_group;\n" ::: "memory");
}
__device__ __forceinline__ void cp_wait0() {
    asm volatile("cp.async.wait_group 0;\n" ::: "memory");
}

// ---------------------------------------------------------------------------
// Main streaming attention kernel: one CTA per (e,a).
// Online softmax over the valid prefix [0, len). Double-buffered 32-token
// tiles. Accumulator u[8][128] lives distributed in registers (4/thread).
// ---------------------------------------------------------------------------
#define TROW 132   // padded tile row (floats); odd*4 stride keeps smem conflict-free

__global__ __launch_bounds__(256, 4) void decoder_main(
    const float* __restrict__ emb,      // [E,A,L,128]
    const int*   __restrict__ lens,     // [E,A]
    const float* __restrict__ wo,       // [8,16,128]
    float*       __restrict__ out)      // [E,A,128]
{
    const int ea = blockIdx.x;
    const int a  = ea & 7;
    int len = lens[ea];
    if (len < 1) len = 1;
    if (len > L_) len = L_;
    const float* embp = emb + (size_t)ea * L_ * 128;

    __shared__ float tile[2][32 * TROW];
    __shared__ float svec_s[8 * TROW];
    __shared__ float bias_s[8];
    __shared__ float sc[32 * 9];
    __shared__ float pp[32 * 9];
    __shared__ float alpha_s[8];
    __shared__ float sums_s[8];
    __shared__ float ctx_s[128];

    const int tid  = threadIdx.x;
    const int wq   = tid >> 5;      // warp id == head for phase 2
    const int lane = tid & 31;
    // phase 1 mapping: thread = (token t1, head hsc)
    const int t1  = tid >> 3, hsc = tid & 7;
    // phase 3 mapping: thread owns u[hA..hB][dp2..dp2+1]
    const int hg  = tid >> 6;       // 0..3
    const int hA  = hg * 2, hB = hA + 1;
    const int dp2 = (tid & 63) * 2;

    // stage s_vec + bias into smem
    for (int i = tid; i < 1024; i += 256) {
        int h = i >> 7, d = i & 127;
        svec_s[h * TROW + d] = g_svec[(ea * H_ + h) * 128 + d];
    }
    if (tid < 8) bias_s[tid] = g_sbias[ea * H_ + tid];

    float u0 = 0.f, u1 = 0.f, u2 = 0.f, u3 = 0.f;
    float mrun = -1e30f, srun = 0.f;     // per-head (warp wq), lane-replicated

    const int ntiles = (len + 31) >> 5;

    // tile loader: 4 x 16B chunks per thread; zero-fill past len
    auto issue = [&](int c, int buf) {
        int base = c * 32;
        #pragma unroll
        for (int kk = 0; kk < 4; ++kk) {
            int idx = tid + kk * 256;          // 0..1023
            int t = idx >> 5, j = idx & 31;
            int l = base + t;
            int lc = l < len ? l : (len - 1);
            const float* src = embp + (size_t)lc * 128 + j * 4;
            int nb = (l < len) ? 16 : 0;
            cp_async16(&tile[buf][t * TROW + j * 4], src, nb);
        }
        cp_commit();
    };

    issue(0, 0);

    for (int c = 0; c < ntiles; ++c) {
        const int buf = c & 1;
        const int base = c * 32;
        cp_wait0();
        __syncthreads();                       // tile c visible to all; prev compute done
        if (c + 1 < ntiles) issue(c + 1, buf ^ 1);

        // ---- phase 1: scores[t,h] = emb[t,:] . svec[h,:] + bias[h]
        {
            float s;
            int l = base + t1;
            if (l < len) {
                const float4* er = (const float4*)&tile[buf][t1 * TROW];
                const float4* sv = (const float4*)&svec_s[hsc * TROW];
                float a0 = 0.f, a1 = 0.f, a2 = 0.f, a3 = 0.f;
                #pragma unroll
                for (int d4 = 0; d4 < 32; ++d4) {
                    float4 e4 = er[d4], s4 = sv[d4];
                    a0 += e4.x * s4.x; a1 += e4.y * s4.y;
                    a2 += e4.z * s4.z; a3 += e4.w * s4.w;
                }
                s = (a0 + a1) + (a2 + a3) + bias_s[hsc];
            } else {
                s = -1e30f;
            }
            sc[t1 * 9 + hsc] = s;
        }
        __syncthreads();

        // ---- phase 2: per-head online softmax (warp wq = head wq, lane = token)
        {
            float sv = sc[lane * 9 + wq];
            float cm = sv;
            #pragma unroll
            for (int o = 16; o; o >>= 1)
                cm = fmaxf(cm, __shfl_xor_sync(0xffffffffu, cm, o));
            float mnew = fmaxf(mrun, cm);
            float al   = __expf(mrun - mnew);
            float p    = __expf(sv - mnew);
            float ps = p;
            #pragma unroll
            for (int o = 16; o; o >>= 1)
                ps += __shfl_xor_sync(0xffffffffu, ps, o);
            srun = srun * al + ps;
            mrun = mnew;
            pp[lane * 9 + wq] = p;
            if (lane == 0) alpha_s[wq] = al;
        }
        __syncthreads();

        // ---- phase 3: u[8][128] += P[8][T] * E[T][128]  (register tiled 2h x 2d)
        {
            float al0 = alpha_s[hA], al1 = alpha_s[hB];
            u0 *= al0; u1 *= al0; u2 *= al1; u3 *= al1;
            int tmax = len - base; if (tmax > 32) tmax = 32;
            const float* tb = &tile[buf][0];
            #pragma unroll 4
            for (int t = 0; t < tmax; ++t) {
                float2 e2 = *(const float2*)&tb[t * TROW + dp2];
                float p0 = pp[t * 9 + hA];
                float p1 = pp[t * 9 + hB];
                u0 += p0 * e2.x; u1 += p0 * e2.y;
                u2 += p1 * e2.x; u3 += p1 * e2.y;
            }
        }
        // no trailing sync needed: next iter's top sync orders tile reuse
    }

    // ---- epilogue
    if (lane == 0) sums_s[wq] = srun;
    __syncthreads();
    {
        float* ub = &tile[0][0];               // reuse tile smem as ubar[8][TROW]
        float i0 = 1.f / sums_s[hA];
        float i1 = 1.f / sums_s[hB];
        ub[hA * TROW + dp2]     = u0 * i0;
        ub[hA * TROW + dp2 + 1] = u1 * i0;
        ub[hB * TROW + dp2]     = u2 * i1;
        ub[hB * TROW + dp2 + 1] = u3 * i1;
    }
    __syncthreads();
    if (tid < 128) {
        // ctx[h*16+k] = sum_d ubar[h][d]*Wv_comb[d][h*16+k] + a*Wv_comb[128][h*16+k]
        const float* ub = &tile[0][0];
        int h = tid >> 4;
        float acc = (float)a * g_wvc[128 * 128 + tid];
        #pragma unroll 4
        for (int d = 0; d < 128; ++d)
            acc += ub[h * TROW + d] * g_wvc[d * 128 + tid];
        ctx_s[tid] = acc;
    }
    __syncthreads();
    if (tid < 128) {
        float o = 0.f;
        #pragma unroll 4
        for (int j = 0; j < 128; ++j)
            o += ctx_s[j] * wo[j * 128 + tid];
        out[ea * 128 + tid] = o;
    }
}

// ---------------------------------------------------------------------------
// kernel_launch
// Inputs (metadata order):
//  0 graph_context [E,D] f32       1 depot_embedding [E,D] f32
//  2 tbd_node_embedding [E,D] f32  3 multi_current_load [E,A] f32
//  4 multi_visited_nodes_embeddings [E,A,L,D] f32
//  5 multi_visited_nodes_len [E,A] i32
//  6 Wq_proj [386,128]  7 Wk_proj [129,128]  8 Wv_proj [129,128]
//  9 Wq [8,128,16]  10 Wk [8,128,16]  11 Wv [8,128,16]  12 Wo [8,16,128]
// ---------------------------------------------------------------------------
extern "C" void kernel_launch(void* const* d_in, const int* in_sizes, int n_in,
                              void* d_out, int out_size)
{
    const float* gc      = (const float*)d_in[0];
    const float* dep     = (const float*)d_in[1];
    const float* tbd     = (const float*)d_in[2];
    const float* load    = (const float*)d_in[3];
    const float* emb     = (const float*)d_in[4];
    const int*   lens    = (const int*)  d_in[5];
    const float* Wq_proj = (const float*)d_in[6];
    const float* Wk_proj = (const float*)d_in[7];
    const float* Wv_proj = (const float*)d_in[8];
    const float* Wq      = (const float*)d_in[9];
    const float* Wk      = (const float*)d_in[10];
    const float* Wv      = (const float*)d_in[11];
    const float* Wo      = (const float*)d_in[12];
    float* out = (float*)d_out;

    precompute_comb<<<258, 128>>>(Wk_proj, Wk, Wv_proj, Wv);
    precompute_svec<<<EA_, 128>>>(gc, dep, tbd, load, Wq_proj, Wq);
    decoder_main<<<EA_, 256>>>(emb, lens, Wo, out);
}

// round 3
// speedup vs baseline: 1.2869x; 1.2869x over previous
#include <cuda_runtime.h>
#include <cuda_bf16.h>
#include <cstdint>

#define E_ 64
#define A_ 8
#define L_ 2048
#define D_ 128
#define H_ 8
#define EA_ (E_*A_)
#define SPLIT 4
#define CHUNK (L_/SPLIT)     // 512 tokens per chunk
#define PPW 12               // pp row stride (floats), 16B-aligned rows

typedef unsigned long long ull;

// ---------------------------------------------------------------------------
// Static device scratch (no cudaMalloc allowed)
// ---------------------------------------------------------------------------
__device__ float g_svec[EA_ * H_ * 128];          // per (e,a,h): score vector (0.25 folded)
__device__ float g_sbias[EA_ * H_];               // per (e,a,h): agent-id score bias
__device__ float g_pu[(size_t)EA_ * SPLIT * 1024];// partial unnormalized ctx  [ea*4+c][h][d]
__device__ float g_pm[EA_ * SPLIT * H_];          // partial max
__device__ float g_ps[EA_ * SPLIT * H_];          // partial sum

// ---------------------------------------------------------------------------
// f32x2 packed helpers
// ---------------------------------------------------------------------------
__device__ __forceinline__ void fma2(ull& c, ull a, ull b) {
    asm("fma.rn.f32x2 %0, %1, %2, %0;" : "+l"(c) : "l"(a), "l"(b));
}
__device__ __forceinline__ void mul2(ull& c, ull a) {
    asm("mul.rn.f32x2 %0, %0, %1;" : "+l"(c) : "l"(a));
}
__device__ __forceinline__ ull pack2(float x, float y) {
    ull r; asm("mov.b64 %0, {%1, %2};" : "=l"(r) : "f"(x), "f"(y)); return r;
}
__device__ __forceinline__ float lo2(ull v) {
    float x; asm("{ .reg .b32 t; mov.b64 {%0, t}, %1; }" : "=f"(x) : "l"(v)); return x;
}
__device__ __forceinline__ float hi2(ull v) {
    float x; asm("{ .reg .b32 t; mov.b64 {t, %0}, %1; }" : "=f"(x) : "l"(v)); return x;
}

// ---------------------------------------------------------------------------
// cp.async helpers
// ---------------------------------------------------------------------------
__device__ __forceinline__ void cp_async16(void* dst, const void* src, int nb) {
    unsigned s = (unsigned)__cvta_generic_to_shared(dst);
    asm volatile("cp.async.cg.shared.global [%0], [%1], 16, %2;\n"
                 :: "r"(s), "l"(src), "r"(nb) : "memory");
}
__device__ __forceinline__ void cp_commit() {
    asm volatile("cp.async.commit_group;\n" ::: "memory");
}
__device__ __forceinline__ void cp_wait0() {
    asm volatile("cp.async.wait_group 0;\n" ::: "memory");
}

// ---------------------------------------------------------------------------
// P1: per-(e,a) query chain fused:  q -> qh -> r = Wk*qh -> svec = Wk_proj*r
// grid = 512 blocks, 128 threads.  (precompute_comb eliminated by
// re-association; 1/sqrt(DK)=0.25 folded into svec/bias.)
// ---------------------------------------------------------------------------
__global__ void precompute_q(const float* __restrict__ gc,
                             const float* __restrict__ dep,
                             const float* __restrict__ tbd,
                             const float* __restrict__ load,
                             const float* __restrict__ Wq_proj,  // [386,128]
                             const float* __restrict__ Wq,       // [8,128,16]
                             const float* __restrict__ Wk_proj,  // [129,128]
                             const float* __restrict__ Wk)       // [8,128,16]
{
    int ea = blockIdx.x;
    int e = ea >> 3, a = ea & 7;
    int tid = threadIdx.x;
    __shared__ float cc[384];
    __shared__ float qs[128];
    __shared__ float qhs[128];
    __shared__ float rr[8 * 128];

    cc[tid]       = gc [e * 128 + tid];
    cc[128 + tid] = dep[e * 128 + tid];
    cc[256 + tid] = tbd[e * 128 + tid];
    __syncthreads();

    // q[d]
    {
        int d = tid;
        float acc = load[e * A_ + a] * Wq_proj[384 * 128 + d]
                  + (float)a          * Wq_proj[385 * 128 + d];
        #pragma unroll 8
        for (int j = 0; j < 384; ++j)
            acc += cc[j] * Wq_proj[j * 128 + d];
        qs[d] = acc;
    }
    __syncthreads();
    // qh[h,k]
    {
        int h = tid >> 4, k = tid & 15;
        float acc = 0.f;
        #pragma unroll 8
        for (int d = 0; d < 128; ++d)
            acc += qs[d] * Wq[h * 2048 + d * 16 + k];
        qhs[tid] = acc;
    }
    __syncthreads();
    // r[h][m] = sum_k Wk[h,m,k]*qh[h,k]
    {
        int h = tid >> 4, mb = tid & 15;
        #pragma unroll
        for (int i = 0; i < 8; ++i) {
            int m = mb * 8 + i;
            float acc = 0.f;
            #pragma unroll
            for (int k = 0; k < 16; ++k)
                acc += Wk[h * 2048 + m * 16 + k] * qhs[h * 16 + k];
            rr[h * 128 + m] = acc;
        }
    }
    __syncthreads();
    // svec[h][d'] = 0.25 * sum_m Wk_proj[d',m]*r[h][m]   (d' = tid)
    {
        int dp = tid;
        const float4* wrow = (const float4*)(Wk_proj + dp * 128);
        #pragma unroll
        for (int h = 0; h < 8; ++h) {
            float a0 = 0.f, a1 = 0.f, a2 = 0.f, a3 = 0.f;
            #pragma unroll 8
            for (int m4 = 0; m4 < 32; ++m4) {
                float4 w4 = wrow[m4];
                a0 += w4.x * rr[h * 128 + m4 * 4 + 0];
                a1 += w4.y * rr[h * 128 + m4 * 4 + 1];
                a2 += w4.z * rr[h * 128 + m4 * 4 + 2];
                a3 += w4.w * rr[h * 128 + m4 * 4 + 3];
            }
            g_svec[(ea * H_ + h) * 128 + dp] = 0.25f * ((a0 + a1) + (a2 + a3));
        }
    }
    // bias (d' = 128 row), threads 0..7
    if (tid < 8) {
        int h = tid;
        float s = 0.f;
        #pragma unroll 8
        for (int m = 0; m < 128; ++m)
            s += Wk_proj[128 * 128 + m] * rr[h * 128 + m];
        g_sbias[ea * H_ + h] = 0.25f * (float)a * s;
    }
}

// ---------------------------------------------------------------------------
// Main streaming kernel: one CTA per (e,a,chunk). grid = 2048, 256 threads.
// Online softmax within the chunk; unnormalized partial (m, s, u) written out.
// ---------------------------------------------------------------------------
__global__ __launch_bounds__(256, 4) void decoder_main(
    const float* __restrict__ emb,      // [E,A,L,128]
    const int*   __restrict__ lens)     // [E,A]
{
    const int bid = blockIdx.x;
    const int ea  = bid >> 2;
    const int chk = bid & 3;
    int len = lens[ea];
    if (len < 1) len = 1;
    if (len > L_) len = L_;
    int nch = len - chk * CHUNK;
    if (nch <= 0) return;                       // empty chunk: partials stay 0
    if (nch > CHUNK) nch = CHUNK;
    const float* embp = emb + (size_t)ea * L_ * 128 + (size_t)chk * CHUNK * 128;

    __shared__ __align__(16) float tile[2][32 * 128];
    __shared__ __align__(16) float svec_s[8 * 128];
    __shared__ __align__(16) float bias_s[8];
    __shared__ __align__(16) float sc[32 * 9];
    __shared__ __align__(16) float pp[32 * PPW];
    __shared__ __align__(16) float alpha_s[8];

    const int tid  = threadIdx.x;
    const int wq   = tid >> 5;       // phase2: warp == head
    const int lane = tid & 31;
    const int t1   = tid >> 3;       // phase1: token
    const int g    = tid & 7;        // phase1: dim group (4 float4s: g+8k)
    const int ts   = tid >> 6;       // phase3: token quarter (8 tokens)
    const int dp2  = tid & 63;       // phase3: dim pair

    // stage svec + bias
    #pragma unroll
    for (int i = 0; i < 4; ++i)
        svec_s[tid + i * 256] = g_svec[ea * 1024 + tid + i * 256];
    if (tid < 8) bias_s[tid] = g_sbias[ea * H_ + tid];

    // phase3 accumulators: u2[hp][j] = (u[2hp][dp2*2+j], u[2hp+1][dp2*2+j])
    ull u2[4][2] = {{0,0},{0,0},{0,0},{0,0}};
    float mrun = -1e30f, srun = 0.f;

    const int ntiles = (nch + 31) >> 5;

    auto issue = [&](int c, int buf) {
        int base = c * 32;
        #pragma unroll
        for (int kk = 0; kk < 4; ++kk) {
            int idx = tid + kk * 256;
            int t = idx >> 5, j = idx & 31;
            int l = base + t;
            int lc = l < nch ? l : (nch - 1);
            const float* src = embp + (size_t)lc * 128 + j * 4;
            int nb = (l < nch) ? 16 : 0;        // zero-fill past end
            cp_async16(&tile[buf][t * 128 + j * 4], src, nb);
        }
        cp_commit();
    };

    issue(0, 0);

    for (int c = 0; c < ntiles; ++c) {
        const int buf = c & 1;
        const int base = c * 32;
        cp_wait0();
        __syncthreads();
        if (c + 1 < ntiles) issue(c + 1, buf ^ 1);

        // ---- phase 1: scores via (t,g) split, f32x2, butterfly reduce
        {
            const float* tb = &tile[buf][t1 * 128];
            ull acc2[8] = {0,0,0,0,0,0,0,0};
            #pragma unroll
            for (int k = 0; k < 4; ++k) {
                int d = g * 4 + 32 * k;
                ull e01 = *(const ull*)&tb[d];
                ull e23 = *(const ull*)&tb[d + 2];
                #pragma unroll
                for (int h = 0; h < 8; ++h) {
                    ull s01 = *(const ull*)&svec_s[h * 128 + d];
                    ull s23 = *(const ull*)&svec_s[h * 128 + d + 2];
                    fma2(acc2[h], e01, s01);
                    fma2(acc2[h], e23, s23);
                }
            }
            float acc[8];
            #pragma unroll
            for (int h = 0; h < 8; ++h) acc[h] = lo2(acc2[h]) + hi2(acc2[h]);
            #pragma unroll
            for (int m = 1; m < 8; m <<= 1) {
                #pragma unroll
                for (int h = 0; h < 8; ++h)
                    acc[h] += __shfl_xor_sync(0xffffffffu, acc[h], m);
            }
            int l = base + t1;
            sc[t1 * 9 + g] = (l < nch) ? (acc[g] + bias_s[g]) : -1e30f;
        }
        __syncthreads();

        // ---- phase 2: per-head online softmax (warp wq, lane = token)
        {
            float sv = sc[lane * 9 + wq];
            float cm = sv;
            #pragma unroll
            for (int o = 16; o; o >>= 1)
                cm = fmaxf(cm, __shfl_xor_sync(0xffffffffu, cm, o));
            float mnew = fmaxf(mrun, cm);
            float al   = __expf(mrun - mnew);
            float p    = __expf(sv - mnew);
            float ps = p;
            #pragma unroll
            for (int o = 16; o; o >>= 1)
                ps += __shfl_xor_sync(0xffffffffu, ps, o);
            srun = srun * al + ps;
            mrun = mnew;
            pp[lane * PPW + wq] = p;
            if (lane == 0) alpha_s[wq] = al;
        }
        __syncthreads();

        // ---- phase 3: u[8][128] += P[8][32]*E[32][128], f32x2, head-paired
        {
            ull a2[4];
            #pragma unroll
            for (int hp = 0; hp < 4; ++hp) {
                a2[hp] = *(const ull*)&alpha_s[2 * hp];
                mul2(u2[hp][0], a2[hp]);
                mul2(u2[hp][1], a2[hp]);
            }
            const float* tb = &tile[buf][0];
            #pragma unroll
            for (int j = 0; j < 8; ++j) {
                int t = ts * 8 + j;
                float2 e2 = *(const float2*)&tb[t * 128 + dp2 * 2];
                ull bx = pack2(e2.x, e2.x);
                ull by = pack2(e2.y, e2.y);
                const float* pr = &pp[t * PPW];
                #pragma unroll
                for (int hp = 0; hp < 4; ++hp) {
                    ull p2 = *(const ull*)&pr[2 * hp];   // (p[2hp], p[2hp+1])
                    fma2(u2[hp][0], p2, bx);
                    fma2(u2[hp][1], p2, by);
                }
            }
        }
    }

    // ---- epilogue: write (m, s), reduce u across 4 token-quarters, store
    if (lane == 0) { g_pm[bid * 8 + wq] = mrun; g_ps[bid * 8 + wq] = srun; }
    __syncthreads();
    float* us = &tile[0][0];          // 4 * 8 * 128 floats = reuse tile smem
    #pragma unroll
    for (int hp = 0; hp < 4; ++hp) {
        us[ts * 1024 + (2*hp  ) * 128 + dp2*2    ] = lo2(u2[hp][0]);
        us[ts * 1024 + (2*hp+1) * 128 + dp2*2    ] = hi2(u2[hp][0]);
        us[ts * 1024 + (2*hp  ) * 128 + dp2*2 + 1] = lo2(u2[hp][1]);
        us[ts * 1024 + (2*hp+1) * 128 + dp2*2 + 1] = hi2(u2[hp][1]);
    }
    __syncthreads();
    #pragma unroll
    for (int k2 = 0; k2 < 4; ++k2) {
        int i = tid + k2 * 256;
        g_pu[(size_t)bid * 1024 + i] = us[i] + us[1024 + i] + us[2048 + i] + us[3072 + i];
    }
}

// ---------------------------------------------------------------------------
// Combine chunks + factored V/O projection. grid = 512, 128 threads.
// ctx[h,k] = sum_m (sum_d ubar[h][d]*Wv_proj[d][m] + a*Wv_proj[128][m]) * Wv[h][m][k]
// out[d]   = sum_j ctx[j]*Wo[j][d]
// ---------------------------------------------------------------------------
__global__ void decoder_reduce(const float* __restrict__ Wv_proj, // [129,128]
                               const float* __restrict__ Wv,      // [8,128,16]
                               const float* __restrict__ Wo,      // [8,16,128]
                               float* __restrict__ out)           // [E,A,128]
{
    int ea = blockIdx.x;
    int a = ea & 7;
    int tid = threadIdx.x;
    __shared__ float w_s[SPLIT * 8];
    __shared__ float sinv[8];
    __shared__ float ub[8 * 128];
    __shared__ float tmp[8 * 128];
    __shared__ float ctx[128];

    if (tid < 8) {
        int h = tid;
        float m0 = g_pm[(ea*4+0)*8+h], m1 = g_pm[(ea*4+1)*8+h];
        float m2 = g_pm[(ea*4+2)*8+h], m3 = g_pm[(ea*4+3)*8+h];
        float s0 = g_ps[(ea*4+0)*8+h], s1 = g_ps[(ea*4+1)*8+h];
        float s2 = g_ps[(ea*4+2)*8+h], s3 = g_ps[(ea*4+3)*8+h];
        // unwritten (empty) chunks have m=0,s=0 -> weight*0 contribution
        float M = fmaxf(fmaxf(m0, m1), fmaxf(m2, m3));
        float w0 = (s0 > 0.f) ? __expf(m0 - M) : 0.f;
        float w1 = (s1 > 0.f) ? __expf(m1 - M) : 0.f;
        float w2 = (s2 > 0.f) ? __expf(m2 - M) : 0.f;
        float w3 = (s3 > 0.f) ? __expf(m3 - M) : 0.f;
        float S = s0*w0 + s1*w1 + s2*w2 + s3*w3;
        w_s[0*8+h] = w0; w_s[1*8+h] = w1; w_s[2*8+h] = w2; w_s[3*8+h] = w3;
        sinv[h] = 1.f / S;
    }
    __syncthreads();

    #pragma unroll
    for (int h = 0; h < 8; ++h) {
        int i = h * 128 + tid;
        float acc = 0.f;
        #pragma unroll
        for (int c = 0; c < 4; ++c)
            acc += g_pu[(size_t)(ea*4+c)*1024 + i] * w_s[c*8+h];
        ub[i] = acc * sinv[h];
    }
    __syncthreads();

    // tmp[h][m], m = tid
    {
        float am = Wv_proj[128 * 128 + tid] * (float)a;
        float t0=am,t1=am,t2=am,t3=am,t4=am,t5=am,t6=am,t7=am;
        #pragma unroll 4
        for (int d = 0; d < 128; ++d) {
            float wpv = Wv_proj[d * 128 + tid];
            t0 += ub[0*128+d]*wpv; t1 += ub[1*128+d]*wpv;
            t2 += ub[2*128+d]*wpv; t3 += ub[3*128+d]*wpv;
            t4 += ub[4*128+d]*wpv; t5 += ub[5*128+d]*wpv;
            t6 += ub[6*128+d]*wpv; t7 += ub[7*128+d]*wpv;
        }
        tmp[0*128+tid]=t0; tmp[1*128+tid]=t1; tmp[2*128+tid]=t2; tmp[3*128+tid]=t3;
        tmp[4*128+tid]=t4; tmp[5*128+tid]=t5; tmp[6*128+tid]=t6; tmp[7*128+tid]=t7;
    }
    __syncthreads();

    // ctx[h*16+k], j = tid
    {
        int h = tid >> 4, k = tid & 15;
        float acc = 0.f;
        #pragma unroll 4
        for (int m = 0; m < 128; ++m)
            acc += tmp[h*128+m] * Wv[h*2048 + m*16 + k];
        ctx[tid] = acc;
    }
    __syncthreads();

    {
        float o = 0.f;
        #pragma unroll 4
        for (int j = 0; j < 128; ++j)
            o += ctx[j] * Wo[j*128 + tid];
        out[ea*128 + tid] = o;
    }
}

// ---------------------------------------------------------------------------
// kernel_launch
// ---------------------------------------------------------------------------
extern "C" void kernel_launch(void* const* d_in, const int* in_sizes, int n_in,
                              void* d_out, int out_size)
{
    const float* gc      = (const float*)d_in[0];
    const float* dep     = (const float*)d_in[1];
    const float* tbd     = (const float*)d_in[2];
    const float* load    = (const float*)d_in[3];
    const float* emb     = (const float*)d_in[4];
    const int*   lens    = (const int*)  d_in[5];
    const float* Wq_proj = (const float*)d_in[6];
    const float* Wk_proj = (const float*)d_in[7];
    const float* Wv_proj = (const float*)d_in[8];
    const float* Wq      = (const float*)d_in[9];
    const float* Wk      = (const float*)d_in[10];
    const float* Wv      = (const float*)d_in[11];
    const float* Wo      = (const float*)d_in[12];
    float* out = (float*)d_out;

    precompute_q<<<EA_, 128>>>(gc, dep, tbd, load, Wq_proj, Wq, Wk_proj, Wk);
    decoder_main<<<EA_ * SPLIT, 256>>>(emb, lens);
    decoder_reduce<<<EA_, 128>>>(Wv_proj, Wv, Wo, out);
}

// round 4
// speedup vs baseline: 1.6883x; 1.3119x over previous
#include <cuda_runtime.h>
#include <cuda_bf16.h>
#include <cstdint>

#define E_ 64
#define A_ 8
#define L_ 2048
#define D_ 128
#define H_ 8
#define EA_ (E_*A_)
#define SPLIT 4
#define CHUNK (L_/SPLIT)     // 512 tokens per chunk
#define PPW 12               // pp row stride (floats)
#define NSLOT 66             // 64 e-slots + unit-load + unit-agentid

typedef unsigned long long ull;

// ---------------------------------------------------------------------------
// Static device scratch
// ---------------------------------------------------------------------------
__device__ float g_svs[NSLOT * H_ * 128];          // svec per slot (0.25 folded)
__device__ float g_sbs[NSLOT * H_];                // score-bias pre-factor per slot
__device__ float g_pu[(size_t)EA_ * SPLIT * 1024]; // partial unnormalized ctx
__device__ float g_pm[EA_ * SPLIT * H_];           // partial max
__device__ float g_ps[EA_ * SPLIT * H_];           // partial sum

// ---------------------------------------------------------------------------
// f32x2 packed helpers
// ---------------------------------------------------------------------------
__device__ __forceinline__ void fma2(ull& c, ull a, ull b) {
    asm("fma.rn.f32x2 %0, %1, %2, %0;" : "+l"(c) : "l"(a), "l"(b));
}
__device__ __forceinline__ void mul2(ull& c, ull a) {
    asm("mul.rn.f32x2 %0, %0, %1;" : "+l"(c) : "l"(a));
}
__device__ __forceinline__ ull pack2(float x, float y) {
    ull r; asm("mov.b64 %0, {%1, %2};" : "=l"(r) : "f"(x), "f"(y)); return r;
}
__device__ __forceinline__ float lo2(ull v) {
    float x; asm("{ .reg .b32 t; mov.b64 {%0, t}, %1; }" : "=f"(x) : "l"(v)); return x;
}
__device__ __forceinline__ float hi2(ull v) {
    float x; asm("{ .reg .b32 t; mov.b64 {t, %0}, %1; }" : "=f"(x) : "l"(v)); return x;
}

// ---------------------------------------------------------------------------
// cp.async helpers
// ---------------------------------------------------------------------------
__device__ __forceinline__ void cp_async16(void* dst, const void* src, int nb) {
    unsigned s = (unsigned)__cvta_generic_to_shared(dst);
    asm volatile("cp.async.cg.shared.global [%0], [%1], 16, %2;\n"
                 :: "r"(s), "l"(src), "r"(nb) : "memory");
}
__device__ __forceinline__ void cp_commit() {
    asm volatile("cp.async.commit_group;\n" ::: "memory");
}
__device__ __forceinline__ void cp_wait0() {
    asm volatile("cp.async.wait_group 0;\n" ::: "memory");
}

// ---------------------------------------------------------------------------
// Precompute per-SLOT query chain. Everything after q is linear in q, and
// q(e,a) = q_ctx(e) + load*Wq_proj[384] + a*Wq_proj[385], so we only need
// NSLOT=66 chains: slots 0..63 = e-contexts, 64 = unit load, 65 = unit aid.
// grid = 66 blocks, 128 threads.
// ---------------------------------------------------------------------------
__global__ void precompute_slots(const float* __restrict__ gc,
                                 const float* __restrict__ dep,
                                 const float* __restrict__ tbd,
                                 const float* __restrict__ Wq_proj,  // [386,128]
                                 const float* __restrict__ Wq,       // [8,128,16]
                                 const float* __restrict__ Wk_proj,  // [129,128]
                                 const float* __restrict__ Wk)       // [8,128,16]
{
    int x = blockIdx.x;
    int tid = threadIdx.x;
    __shared__ float cc[384];
    __shared__ float qs[128];
    __shared__ float qhs[128];
    __shared__ float rr[8 * 128];

    if (x < 64) {
        cc[tid]       = gc [x * 128 + tid];
        cc[128 + tid] = dep[x * 128 + tid];
        cc[256 + tid] = tbd[x * 128 + tid];
    }
    __syncthreads();

    // q[d]
    {
        int d = tid;
        float acc = 0.f;
        if (x == 64) acc = Wq_proj[384 * 128 + d];
        else if (x == 65) acc = Wq_proj[385 * 128 + d];
        else {
            #pragma unroll 8
            for (int j = 0; j < 384; ++j)
                acc += cc[j] * Wq_proj[j * 128 + d];
        }
        qs[d] = acc;
    }
    __syncthreads();
    // qh[h,k]
    {
        int h = tid >> 4, k = tid & 15;
        float acc = 0.f;
        #pragma unroll 8
        for (int d = 0; d < 128; ++d)
            acc += qs[d] * Wq[h * 2048 + d * 16 + k];
        qhs[tid] = acc;
    }
    __syncthreads();
    // r[h][m] = sum_k Wk[h,m,k]*qh[h,k]
    {
        int h = tid >> 4, mb = tid & 15;
        #pragma unroll
        for (int i = 0; i < 8; ++i) {
            int m = mb * 8 + i;
            float acc = 0.f;
            #pragma unroll
            for (int k = 0; k < 16; ++k)
                acc += Wk[h * 2048 + m * 16 + k] * qhs[h * 16 + k];
            rr[h * 128 + m] = acc;
        }
    }
    __syncthreads();
    // svec_slot[h][d'] = 0.25 * sum_m Wk_proj[d',m]*r[h][m]
    {
        int dp = tid;
        const float4* wrow = (const float4*)(Wk_proj + dp * 128);
        #pragma unroll
        for (int h = 0; h < 8; ++h) {
            float a0 = 0.f, a1 = 0.f, a2 = 0.f, a3 = 0.f;
            #pragma unroll 8
            for (int m4 = 0; m4 < 32; ++m4) {
                float4 w4 = wrow[m4];
                a0 += w4.x * rr[h * 128 + m4 * 4 + 0];
                a1 += w4.y * rr[h * 128 + m4 * 4 + 1];
                a2 += w4.z * rr[h * 128 + m4 * 4 + 2];
                a3 += w4.w * rr[h * 128 + m4 * 4 + 3];
            }
            g_svs[(x * 8 + h) * 128 + dp] = 0.25f * ((a0 + a1) + (a2 + a3));
        }
    }
    // bias pre-factor (d' = 128 row)
    if (tid < 8) {
        int h = tid;
        float s = 0.f;
        #pragma unroll 8
        for (int m = 0; m < 128; ++m)
            s += Wk_proj[128 * 128 + m] * rr[h * 128 + m];
        g_sbs[x * 8 + h] = 0.25f * s;
    }
}

// ---------------------------------------------------------------------------
// Main streaming kernel: one CTA per (e,a,chunk). grid = 2048, 256 threads.
// ---------------------------------------------------------------------------
__global__ __launch_bounds__(256, 3) void decoder_main(
    const float* __restrict__ emb,      // [E,A,L,128]
    const int*   __restrict__ lens,     // [E,A]
    const float* __restrict__ loadv)    // [E,A]
{
    const int bid = blockIdx.x;
    const int ea  = bid >> 2;
    const int chk = bid & 3;
    const int e   = ea >> 3;
    const float af = (float)(ea & 7);
    int len = lens[ea];
    if (len < 1) len = 1;
    if (len > L_) len = L_;
    int nch = len - chk * CHUNK;
    if (nch <= 0) return;                       // empty chunk: partials stay 0
    if (nch > CHUNK) nch = CHUNK;
    const float* embp = emb + (size_t)ea * L_ * 128 + (size_t)chk * CHUNK * 128;

    __shared__ __align__(16) float tile[2][32 * 128];
    __shared__ __align__(16) float svec_s[8 * 128];
    __shared__ __align__(16) float bias_s[8];
    __shared__ __align__(16) float sc[32 * 9];
    __shared__ __align__(16) float pp[32 * PPW];
    __shared__ __align__(16) float alpha_s[8];

    const int tid  = threadIdx.x;
    const int wq   = tid >> 5;       // phase2: warp == head; phase3: token group
    const int lane = tid & 31;
    const int t1   = tid >> 3;       // phase1: token
    const int g    = tid & 7;        // phase1: dim group

    // stage svec + bias: slot combination (linear in load and agent id)
    {
        float lv = loadv[ea];
        #pragma unroll
        for (int i = 0; i < 4; ++i) {
            int idx = tid + i * 256;   // h*128+d
            svec_s[idx] = g_svs[e * 1024 + idx]
                        + lv * g_svs[64 * 1024 + idx]
                        + af * g_svs[65 * 1024 + idx];
        }
        if (tid < 8)
            bias_s[tid] = af * (g_sbs[e * 8 + tid]
                              + lv * g_sbs[64 * 8 + tid]
                              + af * g_sbs[65 * 8 + tid]);
    }

    // phase3 accumulators: u2[hp][dj] = (u[2hp][lane*4+dj], u[2hp+1][lane*4+dj])
    ull u2[4][4] = {{0,0,0,0},{0,0,0,0},{0,0,0,0},{0,0,0,0}};
    float mrun = -1e30f, srun = 0.f;

    const int ntiles = (nch + 31) >> 5;

    auto issue = [&](int c, int buf) {
        int base = c * 32;
        #pragma unroll
        for (int kk = 0; kk < 4; ++kk) {
            int idx = tid + kk * 256;
            int t = idx >> 5, j = idx & 31;
            int l = base + t;
            int lc = l < nch ? l : (nch - 1);
            const float* src = embp + (size_t)lc * 128 + j * 4;
            int nb = (l < nch) ? 16 : 0;        // zero-fill past end
            cp_async16(&tile[buf][t * 128 + j * 4], src, nb);
        }
        cp_commit();
    };

    issue(0, 0);

    for (int c = 0; c < ntiles; ++c) {
        const int buf = c & 1;
        const int base = c * 32;
        cp_wait0();
        __syncthreads();
        if (c + 1 < ntiles) issue(c + 1, buf ^ 1);

        // ---- phase 1: scores via (t,g) split, b128 smem loads, f32x2 FMA
        {
            const float* tb = &tile[buf][t1 * 128];
            ull acc2[8] = {0,0,0,0,0,0,0,0};
            #pragma unroll
            for (int k = 0; k < 4; ++k) {
                int d = g * 4 + 32 * k;
                longlong2 ev = *(const longlong2*)&tb[d];
                #pragma unroll
                for (int h = 0; h < 8; ++h) {
                    longlong2 sv = *(const longlong2*)&svec_s[h * 128 + d];
                    fma2(acc2[h], (ull)ev.x, (ull)sv.x);
                    fma2(acc2[h], (ull)ev.y, (ull)sv.y);
                }
            }
            float acc[8];
            #pragma unroll
            for (int h = 0; h < 8; ++h) acc[h] = lo2(acc2[h]) + hi2(acc2[h]);
            #pragma unroll
            for (int m = 1; m < 8; m <<= 1) {
                #pragma unroll
                for (int h = 0; h < 8; ++h)
                    acc[h] += __shfl_xor_sync(0xffffffffu, acc[h], m);
            }
            int l = base + t1;
            sc[t1 * 9 + g] = (l < nch) ? (acc[g] + bias_s[g]) : -1e30f;
        }
        __syncthreads();

        // ---- phase 2: per-head online softmax (warp wq = head, lane = token)
        {
            float sv = sc[lane * 9 + wq];
            float cm = sv;
            #pragma unroll
            for (int o = 16; o; o >>= 1)
                cm = fmaxf(cm, __shfl_xor_sync(0xffffffffu, cm, o));
            float mnew = fmaxf(mrun, cm);
            float al   = __expf(mrun - mnew);
            float p    = __expf(sv - mnew);
            float ps = p;
            #pragma unroll
            for (int o = 16; o; o >>= 1)
                ps += __shfl_xor_sync(0xffffffffu, ps, o);
            srun = srun * al + ps;
            mrun = mnew;
            pp[lane * PPW + wq] = p;
            if (lane == 0) alpha_s[wq] = al;
        }
        __syncthreads();

        // ---- phase 3: warp = token group (4 tokens), lane = 4-dim slice
        {
            ull a2[4];
            #pragma unroll
            for (int hp = 0; hp < 4; ++hp) {
                a2[hp] = *(const ull*)&alpha_s[2 * hp];
                #pragma unroll
                for (int dj = 0; dj < 4; ++dj) mul2(u2[hp][dj], a2[hp]);
            }
            const float* tb = &tile[buf][0];
            #pragma unroll
            for (int j = 0; j < 4; ++j) {
                int t = wq * 4 + j;
                float4 e4 = *(const float4*)&tb[t * 128 + lane * 4];
                ull ex = pack2(e4.x, e4.x);
                ull ey = pack2(e4.y, e4.y);
                ull ez = pack2(e4.z, e4.z);
                ull ew = pack2(e4.w, e4.w);
                const float* pr = &pp[t * PPW];
                #pragma unroll
                for (int hp = 0; hp < 4; ++hp) {
                    ull p2 = *(const ull*)&pr[2 * hp];   // (p[2hp], p[2hp+1])
                    fma2(u2[hp][0], p2, ex);
                    fma2(u2[hp][1], p2, ey);
                    fma2(u2[hp][2], p2, ez);
                    fma2(u2[hp][3], p2, ew);
                }
            }
        }
    }

    // ---- epilogue: write (m, s); reduce u over 8 token groups; store
    if (lane == 0) { g_pm[bid * 8 + wq] = mrun; g_ps[bid * 8 + wq] = srun; }
    __syncthreads();
    float* us = &tile[0][0];          // 8 groups * 8 heads * 128 dims = 32KB
    #pragma unroll
    for (int hp = 0; hp < 4; ++hp) {
        float4 v0 = make_float4(lo2(u2[hp][0]), lo2(u2[hp][1]),
                                lo2(u2[hp][2]), lo2(u2[hp][3]));
        float4 v1 = make_float4(hi2(u2[hp][0]), hi2(u2[hp][1]),
                                hi2(u2[hp][2]), hi2(u2[hp][3]));
        *(float4*)&us[wq * 1024 + (2*hp  ) * 128 + lane * 4] = v0;
        *(float4*)&us[wq * 1024 + (2*hp+1) * 128 + lane * 4] = v1;
    }
    __syncthreads();
    #pragma unroll
    for (int k2 = 0; k2 < 4; ++k2) {
        int i = tid + k2 * 256;
        float s = 0.f;
        #pragma unroll
        for (int tg = 0; tg < 8; ++tg) s += us[tg * 1024 + i];
        g_pu[(size_t)bid * 1024 + i] = s;
    }
}

// ---------------------------------------------------------------------------
// Combine chunks + factored V/O projection. grid = 512, 128 threads.
// ---------------------------------------------------------------------------
__global__ void decoder_reduce(const float* __restrict__ Wv_proj, // [129,128]
                               const float* __restrict__ Wv,      // [8,128,16]
                               const float* __restrict__ Wo,      // [8,16,128]
                               float* __restrict__ out)           // [E,A,128]
{
    int ea = blockIdx.x;
    int a = ea & 7;
    int tid = threadIdx.x;
    __shared__ float w_s[SPLIT * 8];
    __shared__ float sinv[8];
    __shared__ float ub[8 * 128];
    __shared__ float tmp[8 * 128];
    __shared__ float ctx[128];

    if (tid < 8) {
        int h = tid;
        float m0 = g_pm[(ea*4+0)*8+h], m1 = g_pm[(ea*4+1)*8+h];
        float m2 = g_pm[(ea*4+2)*8+h], m3 = g_pm[(ea*4+3)*8+h];
        float s0 = g_ps[(ea*4+0)*8+h], s1 = g_ps[(ea*4+1)*8+h];
        float s2 = g_ps[(ea*4+2)*8+h], s3 = g_ps[(ea*4+3)*8+h];
        float M = fmaxf(fmaxf(m0, m1), fmaxf(m2, m3));
        float w0 = (s0 > 0.f) ? __expf(m0 - M) : 0.f;
        float w1 = (s1 > 0.f) ? __expf(m1 - M) : 0.f;
        float w2 = (s2 > 0.f) ? __expf(m2 - M) : 0.f;
        float w3 = (s3 > 0.f) ? __expf(m3 - M) : 0.f;
        float S = s0*w0 + s1*w1 + s2*w2 + s3*w3;
        w_s[0*8+h] = w0; w_s[1*8+h] = w1; w_s[2*8+h] = w2; w_s[3*8+h] = w3;
        sinv[h] = 1.f / S;
    }
    __syncthreads();

    #pragma unroll
    for (int h = 0; h < 8; ++h) {
        int i = h * 128 + tid;
        float acc = 0.f;
        #pragma unroll
        for (int c = 0; c < 4; ++c)
            acc += g_pu[(size_t)(ea*4+c)*1024 + i] * w_s[c*8+h];
        ub[i] = acc * sinv[h];
    }
    __syncthreads();

    // tmp[h][m], m = tid
    {
        float am = Wv_proj[128 * 128 + tid] * (float)a;
        float t0=am,t1=am,t2=am,t3=am,t4=am,t5=am,t6=am,t7=am;
        #pragma unroll 4
        for (int d = 0; d < 128; ++d) {
            float wpv = Wv_proj[d * 128 + tid];
            t0 += ub[0*128+d]*wpv; t1 += ub[1*128+d]*wpv;
            t2 += ub[2*128+d]*wpv; t3 += ub[3*128+d]*wpv;
            t4 += ub[4*128+d]*wpv; t5 += ub[5*128+d]*wpv;
            t6 += ub[6*128+d]*wpv; t7 += ub[7*128+d]*wpv;
        }
        tmp[0*128+tid]=t0; tmp[1*128+tid]=t1; tmp[2*128+tid]=t2; tmp[3*128+tid]=t3;
        tmp[4*128+tid]=t4; tmp[5*128+tid]=t5; tmp[6*128+tid]=t6; tmp[7*128+tid]=t7;
    }
    __syncthreads();

    // ctx[h*16+k]
    {
        int h = tid >> 4, k = tid & 15;
        float acc = 0.f;
        #pragma unroll 4
        for (int m = 0; m < 128; ++m)
            acc += tmp[h*128+m] * Wv[h*2048 + m*16 + k];
        ctx[tid] = acc;
    }
    __syncthreads();

    {
        float o = 0.f;
        #pragma unroll 4
        for (int j = 0; j < 128; ++j)
            o += ctx[j] * Wo[j*128 + tid];
        out[ea*128 + tid] = o;
    }
}

// ---------------------------------------------------------------------------
// kernel_launch
// ---------------------------------------------------------------------------
extern "C" void kernel_launch(void* const* d_in, const int* in_sizes, int n_in,
                              void* d_out, int out_size)
{
    const float* gc      = (const float*)d_in[0];
    const float* dep     = (const float*)d_in[1];
    const float* tbd     = (const float*)d_in[2];
    const float* load    = (const float*)d_in[3];
    const float* emb     = (const float*)d_in[4];
    const int*   lens    = (const int*)  d_in[5];
    const float* Wq_proj = (const float*)d_in[6];
    const float* Wk_proj = (const float*)d_in[7];
    const float* Wv_proj = (const float*)d_in[8];
    const float* Wq      = (const float*)d_in[9];
    const float* Wk      = (const float*)d_in[10];
    const float* Wv      = (const float*)d_in[11];
    const float* Wo      = (const float*)d_in[12];
    float* out = (float*)d_out;

    precompute_slots<<<NSLOT, 128>>>(gc, dep, tbd, Wq_proj, Wq, Wk_proj, Wk);
    decoder_main<<<EA_ * SPLIT, 256>>>(emb, lens, load);
    decoder_reduce<<<EA_, 128>>>(Wv_proj, Wv, Wo, out);
}